// round 5
// baseline (speedup 1.0000x reference)
#include <cuda_runtime.h>
#include <cstdint>

// ---------------------------------------------------------------------------
// PrunedGroupSum: y[b,g] = (sum over contiguous column group g of x[b,:]) / 20
//   x:           [B, D] float32   (B=1024, D=262144 -> 1 GiB, streaming)
//   group_sizes: [K]    int32     (K=1000, sums to D)
//   out:         [B, K] float32
//
// R5: uniform work decomposition. Groups are split into fixed 256-col chunks
// (work items). warp = (chunk, 8 rows): <=2 vector iterations per warp ->
// near-perfect balance; 8 independent LDG.128 per iteration for MLP.
// Partials atomically added into zero-initialized out.
// ---------------------------------------------------------------------------

#define MAX_K      4096
#define MAX_ITEMS  8192
#define CHUNK      256
#define ROWS_PER_WARP 8

__device__ int g_offsets[MAX_K + 1];
__device__ int g_nitems;
__device__ int g_item_g[MAX_ITEMS];
__device__ int g_item_s[MAX_ITEMS];
__device__ int g_item_e[MAX_ITEMS];

// 1-block builder: scan group_sizes -> offsets; split groups into CHUNK-col
// work items via a second scan of per-group chunk counts. K <= 1024.
__global__ void pgs_build_kernel(const int* __restrict__ gs, int K) {
    __shared__ int sh[1024];
    __shared__ int sh2[1024];
    int t = threadIdx.x;

    // scan 1: group offsets
    int v = (t < K) ? gs[t] : 0;
    sh[t] = v;
    __syncthreads();
#pragma unroll
    for (int off = 1; off < 1024; off <<= 1) {
        int add = (t >= off) ? sh[t - off] : 0;
        __syncthreads();
        sh[t] += add;
        __syncthreads();
    }
    if (t == 0) g_offsets[0] = 0;
    if (t < K) g_offsets[t + 1] = sh[t];
    __syncthreads();

    // scan 2: per-group chunk counts -> item base offsets
    int size = (t < K) ? gs[t] : 0;
    int nch = (size + CHUNK - 1) / CHUNK;
    sh2[t] = nch;
    __syncthreads();
#pragma unroll
    for (int off = 1; off < 1024; off <<= 1) {
        int add = (t >= off) ? sh2[t - off] : 0;
        __syncthreads();
        sh2[t] += add;
        __syncthreads();
    }
    if (t == K - 1 || (t == 1023 && K > 1024)) g_nitems = sh2[K - 1];
    if (t < K) {
        int base = sh2[t] - nch;          // exclusive prefix
        int s = (t == 0) ? 0 : sh[t - 1]; // group start
        int e = sh[t];                    // group end
        for (int i = 0; i < nch; i++) {
            int cs = s + i * CHUNK;
            int ce = cs + CHUNK; if (ce > e) ce = e;
            g_item_g[base + i] = t;
            g_item_s[base + i] = cs;
            g_item_e[base + i] = ce;
        }
    }
}

__global__ void pgs_zero_kernel(float* __restrict__ out, int n4) {
    int i = blockIdx.x * blockDim.x + threadIdx.x;
    if (i < n4) reinterpret_cast<float4*>(out)[i] = make_float4(0.f, 0.f, 0.f, 0.f);
}

__device__ __forceinline__ float hsum4(float4 v) {
    return (v.x + v.y) + (v.z + v.w);
}

__global__ __launch_bounds__(128, 6) void pgs_sum_chunks_kernel(
    const float* __restrict__ x,
    float* __restrict__ out,
    int D, int K, int B)
{
    int item = blockIdx.x * 4 + (threadIdx.x >> 5);
    if (item >= g_nitems) return;
    int lane = threadIdx.x & 31;
    int row0 = blockIdx.y * ROWS_PER_WARP;
    int nrows = B - row0;
    if (nrows > ROWS_PER_WARP) nrows = ROWS_PER_WARP;

    int g = g_item_g[item];
    int s = g_item_s[item];
    int e = g_item_e[item];

    const float* p = x + (size_t)row0 * (size_t)D;
    const size_t SD = (size_t)D;

    float acc[ROWS_PER_WARP];
#pragma unroll
    for (int r = 0; r < ROWS_PER_WARP; r++) acc[r] = 0.0f;

    int s4 = (s + 3) & ~3;
    int e4 = e & ~3;

    if (nrows == ROWS_PER_WARP) {
        if (s4 >= e4) {
            for (int c = s + lane; c < e; c += 32) {
#pragma unroll
                for (int r = 0; r < ROWS_PER_WARP; r++)
                    acc[r] += __ldcs(p + (size_t)r * SD + c);
            }
        } else {
            // head (<=3 scalar cols)
            {
                int c = s + lane;
                if (c < s4) {
#pragma unroll
                    for (int r = 0; r < ROWS_PER_WARP; r++)
                        acc[r] += __ldcs(p + (size_t)r * SD + c);
                }
            }
            // main: at most 2 iterations (CHUNK=256); 8 independent LDG.128 each
            for (int c4 = s4 + lane * 4; c4 < e4; c4 += 128) {
                float4 v[ROWS_PER_WARP];
#pragma unroll
                for (int r = 0; r < ROWS_PER_WARP; r++)
                    v[r] = __ldcs(reinterpret_cast<const float4*>(p + (size_t)r * SD + c4));
#pragma unroll
                for (int r = 0; r < ROWS_PER_WARP; r++)
                    acc[r] += hsum4(v[r]);
            }
            // tail (<=3 scalar cols)
            {
                int c = e4 + lane;
                if (c < e) {
#pragma unroll
                    for (int r = 0; r < ROWS_PER_WARP; r++)
                        acc[r] += __ldcs(p + (size_t)r * SD + c);
                }
            }
        }
    } else {
        for (int r = 0; r < nrows; r++) {
            const float* pr = p + (size_t)r * SD;
            float a = 0.f;
            for (int c = s + lane; c < e; c += 32) a += __ldcs(pr + c);
            acc[r] = a;
        }
    }

#pragma unroll
    for (int r = 0; r < ROWS_PER_WARP; r++) {
#pragma unroll
        for (int o = 16; o > 0; o >>= 1)
            acc[r] += __shfl_xor_sync(0xffffffffu, acc[r], o);
    }

    if (lane == 0) {
        const float inv_tau = 1.0f / 20.0f;
        float* ob = out + (size_t)row0 * (size_t)K + g;
#pragma unroll
        for (int r = 0; r < ROWS_PER_WARP; r++)
            if (r < nrows) atomicAdd(ob + (size_t)r * (size_t)K, acc[r] * inv_tau);
    }
}

extern "C" void kernel_launch(void* const* d_in, const int* in_sizes, int n_in,
                              void* d_out, int out_size) {
    const float* x  = (const float*)d_in[0];
    const int*   gs = (const int*)d_in[1];

    int K = in_sizes[1];
    int B = out_size / K;
    int D = in_sizes[0] / B;

    float* out = (float*)d_out;

    pgs_build_kernel<<<1, 1024>>>(gs, K);

    int n4 = out_size / 4;  // B*K divisible by 4 here (1024*1000)
    pgs_zero_kernel<<<(n4 + 255) / 256, 256>>>(out, n4);

    int max_items = K + D / CHUNK + 1;   // upper bound on g_nitems
    dim3 grid((max_items + 3) / 4, (B + ROWS_PER_WARP - 1) / ROWS_PER_WARP);
    pgs_sum_chunks_kernel<<<grid, 128>>>(x, out, D, K, B);
}

// round 6
// speedup vs baseline: 1.1821x; 1.1821x over previous
#include <cuda_runtime.h>
#include <cstdint>

// ---------------------------------------------------------------------------
// PrunedGroupSum: y[b,g] = (sum over contiguous column group g of x[b,:]) / 20
//   x:           [B, D] float32   (B=1024, D=262144 -> 1 GiB, streaming)
//   group_sizes: [K]    int32     (K=1000, sums to D)
//   out:         [B, K] float32
//
// R6: R4 structure (warp = (group, 8 rows), 8 independent LDG.128/iter) plus
// size-sorted group scheduling: builder bitonic-sorts groups by size (desc)
// so the 4 warps of a block get similar-sized groups -> no intra-block
// stranding (R4's achieved occ was 27% vs 37.5% theoretical due to E[max of
// 4 iid exponential] ~ 2.1x mean). No atomics, single pass over x.
// ---------------------------------------------------------------------------

#define MAX_K 4096
#define ROWS_PER_WARP 8
#define SORT_N 1024

__device__ int g_offsets[MAX_K + 1];
__device__ int g_order[SORT_N];   // group ids sorted by size, descending

// 1-block builder: prefix scan of group_sizes -> offsets, then bitonic sort
// of (size, id) descending -> g_order. Requires K <= 1024.
__global__ void pgs_build_kernel(const int* __restrict__ gs, int K) {
    __shared__ int sh[SORT_N];
    __shared__ int key[SORT_N];
    __shared__ int val[SORT_N];
    int t = threadIdx.x;

    // ---- scan: group offsets ----
    int v = (t < K) ? gs[t] : 0;
    sh[t] = v;
    __syncthreads();
#pragma unroll
    for (int off = 1; off < SORT_N; off <<= 1) {
        int add = (t >= off) ? sh[t - off] : 0;
        __syncthreads();
        sh[t] += add;
        __syncthreads();
    }
    if (t == 0) g_offsets[0] = 0;
    if (t < K) g_offsets[t + 1] = sh[t];

    // ---- bitonic sort by size, descending ----
    key[t] = (t < K) ? gs[t] : -1;   // pad sorts to the end
    val[t] = t;
    __syncthreads();

    for (int k = 2; k <= SORT_N; k <<= 1) {
        for (int j = k >> 1; j > 0; j >>= 1) {
            int ixj = t ^ j;
            if (ixj > t) {
                bool desc_block = ((t & k) == 0);   // descending overall
                int kt = key[t], ki = key[ixj];
                bool swap = desc_block ? (kt < ki) : (kt > ki);
                if (swap) {
                    int vt = val[t];
                    key[t] = ki; key[ixj] = kt;
                    val[t] = val[ixj]; val[ixj] = vt;
                }
            }
            __syncthreads();
        }
    }
    g_order[t] = val[t];
}

__device__ __forceinline__ float hsum4(float4 v) {
    return (v.x + v.y) + (v.z + v.w);
}

__global__ __launch_bounds__(128, 6) void pgs_sum8_kernel(
    const float* __restrict__ x,
    float* __restrict__ out,
    int D, int K, int B)
{
    int item = blockIdx.x * 4 + (threadIdx.x >> 5);
    if (item >= K) return;
    int g = g_order[item];

    int lane = threadIdx.x & 31;
    int row0 = blockIdx.y * ROWS_PER_WARP;
    int nrows = B - row0;
    if (nrows > ROWS_PER_WARP) nrows = ROWS_PER_WARP;

    int s = g_offsets[g];
    int e = g_offsets[g + 1];

    const float* p = x + (size_t)row0 * (size_t)D;
    const size_t SD = (size_t)D;

    float acc[ROWS_PER_WARP];
#pragma unroll
    for (int r = 0; r < ROWS_PER_WARP; r++) acc[r] = 0.0f;

    int s4 = (s + 3) & ~3;
    int e4 = e & ~3;

    if (nrows == ROWS_PER_WARP) {
        if (s4 >= e4) {
            // tiny group: scalar, coalesced across lanes, 8 streams
            for (int c = s + lane; c < e; c += 32) {
#pragma unroll
                for (int r = 0; r < ROWS_PER_WARP; r++)
                    acc[r] += __ldcs(p + (size_t)r * SD + c);
            }
        } else {
            // head (<=3 scalar cols)
            {
                int c = s + lane;
                if (c < s4) {
#pragma unroll
                    for (int r = 0; r < ROWS_PER_WARP; r++)
                        acc[r] += __ldcs(p + (size_t)r * SD + c);
                }
            }
            // main: 8 independent LDG.128 staged before any accumulation
            for (int c4 = s4 + lane * 4; c4 < e4; c4 += 128) {
                float4 v[ROWS_PER_WARP];
#pragma unroll
                for (int r = 0; r < ROWS_PER_WARP; r++)
                    v[r] = __ldcs(reinterpret_cast<const float4*>(p + (size_t)r * SD + c4));
#pragma unroll
                for (int r = 0; r < ROWS_PER_WARP; r++)
                    acc[r] += hsum4(v[r]);
            }
            // tail (<=3 scalar cols)
            {
                int c = e4 + lane;
                if (c < e) {
#pragma unroll
                    for (int r = 0; r < ROWS_PER_WARP; r++)
                        acc[r] += __ldcs(p + (size_t)r * SD + c);
                }
            }
        }
    } else {
        // remainder rows: simple per-row scalar path
        for (int r = 0; r < nrows; r++) {
            const float* pr = p + (size_t)r * SD;
            float a = 0.f;
            for (int c = s + lane; c < e; c += 32) a += __ldcs(pr + c);
            acc[r] = a;
        }
    }

    // butterfly reduce all 8 accumulators
#pragma unroll
    for (int r = 0; r < ROWS_PER_WARP; r++) {
#pragma unroll
        for (int o = 16; o > 0; o >>= 1)
            acc[r] += __shfl_xor_sync(0xffffffffu, acc[r], o);
    }

    if (lane == 0) {
        const float inv_tau = 1.0f / 20.0f;
        size_t ob = (size_t)row0 * (size_t)K + g;
#pragma unroll
        for (int r = 0; r < ROWS_PER_WARP; r++)
            if (r < nrows) out[ob + (size_t)r * (size_t)K] = acc[r] * inv_tau;
    }
}

extern "C" void kernel_launch(void* const* d_in, const int* in_sizes, int n_in,
                              void* d_out, int out_size) {
    const float* x  = (const float*)d_in[0];
    const int*   gs = (const int*)d_in[1];

    int K = in_sizes[1];
    int B = out_size / K;
    int D = in_sizes[0] / B;

    float* out = (float*)d_out;

    pgs_build_kernel<<<1, SORT_N>>>(gs, K);

    dim3 grid((K + 3) / 4, (B + ROWS_PER_WARP - 1) / ROWS_PER_WARP);
    pgs_sum8_kernel<<<grid, 128>>>(x, out, D, K, B);
}

// round 7
// speedup vs baseline: 1.3099x; 1.1081x over previous
#include <cuda_runtime.h>
#include <cstdint>

// ---------------------------------------------------------------------------
// PrunedGroupSum: y[b,g] = (sum over contiguous column group g of x[b,:]) / 20
//   x:           [B, D] float32   (B=1024, D=262144 -> 1 GiB, streaming)
//   group_sizes: [K]    int32     (K=1000, sums to D)
//   out:         [B, K] float32
//
// R7: block = (one group, 32 rows); each of 4 warps takes an 8-row slice of
// the SAME group -> exact intra-block balance, no sort needed (scan-only
// builder). Column loop unrolled x2 with launch_bounds(128,5) so 16 LDG.128
// live simultaneously (double-buffered; loads stay in flight through the
// accumulate phase). No atomics, single pass over x.
// ---------------------------------------------------------------------------

#define MAX_K 4096
#define ROWS_PER_WARP 8
#define ROWS_PER_BLOCK 32

__device__ int g_offsets[MAX_K + 1];

// 1-block Hillis-Steele inclusive scan of group_sizes (K <= 1024; K=1000 here).
__global__ void pgs_scan_kernel(const int* __restrict__ gs, int K) {
    __shared__ int sh[1024];
    int t = threadIdx.x;
    int v = (t < K) ? gs[t] : 0;
    sh[t] = v;
    __syncthreads();
#pragma unroll
    for (int off = 1; off < 1024; off <<= 1) {
        int add = (t >= off) ? sh[t - off] : 0;
        __syncthreads();
        sh[t] += add;
        __syncthreads();
    }
    if (t == 0) g_offsets[0] = 0;
    if (t < K) g_offsets[t + 1] = sh[t];
}

__device__ __forceinline__ float hsum4(float4 v) {
    return (v.x + v.y) + (v.z + v.w);
}

__global__ __launch_bounds__(128, 5) void pgs_sum_kernel(
    const float* __restrict__ x,
    float* __restrict__ out,
    int D, int K, int B)
{
    int g = blockIdx.x;
    int warp = threadIdx.x >> 5;
    int lane = threadIdx.x & 31;

    int row0 = blockIdx.y * ROWS_PER_BLOCK + warp * ROWS_PER_WARP;
    int nrows = B - row0;
    if (nrows <= 0) return;
    if (nrows > ROWS_PER_WARP) nrows = ROWS_PER_WARP;

    int s = g_offsets[g];
    int e = g_offsets[g + 1];

    const float* p = x + (size_t)row0 * (size_t)D;
    const size_t SD = (size_t)D;

    float acc[ROWS_PER_WARP];
#pragma unroll
    for (int r = 0; r < ROWS_PER_WARP; r++) acc[r] = 0.0f;

    int s4 = (s + 3) & ~3;
    int e4 = e & ~3;

    if (nrows == ROWS_PER_WARP) {
        if (s4 >= e4) {
            // tiny group: scalar, coalesced across lanes, 8 streams
            for (int c = s + lane; c < e; c += 32) {
#pragma unroll
                for (int r = 0; r < ROWS_PER_WARP; r++)
                    acc[r] += __ldcs(p + (size_t)r * SD + c);
            }
        } else {
            // head (<=3 scalar cols)
            {
                int c = s + lane;
                if (c < s4) {
#pragma unroll
                    for (int r = 0; r < ROWS_PER_WARP; r++)
                        acc[r] += __ldcs(p + (size_t)r * SD + c);
                }
            }
            int c4 = s4 + lane * 4;
            // unroll-2 main: 16 independent LDG.128 live at once
            for (; c4 + 128 < e4; c4 += 256) {
                float4 v[ROWS_PER_WARP];
                float4 w[ROWS_PER_WARP];
#pragma unroll
                for (int r = 0; r < ROWS_PER_WARP; r++)
                    v[r] = __ldcs(reinterpret_cast<const float4*>(p + (size_t)r * SD + c4));
#pragma unroll
                for (int r = 0; r < ROWS_PER_WARP; r++)
                    w[r] = __ldcs(reinterpret_cast<const float4*>(p + (size_t)r * SD + c4 + 128));
#pragma unroll
                for (int r = 0; r < ROWS_PER_WARP; r++)
                    acc[r] += hsum4(v[r]) + hsum4(w[r]);
            }
            // remainder vector tile (0 or 1 per lane)
            if (c4 < e4) {
                float4 v[ROWS_PER_WARP];
#pragma unroll
                for (int r = 0; r < ROWS_PER_WARP; r++)
                    v[r] = __ldcs(reinterpret_cast<const float4*>(p + (size_t)r * SD + c4));
#pragma unroll
                for (int r = 0; r < ROWS_PER_WARP; r++)
                    acc[r] += hsum4(v[r]);
            }
            // tail (<=3 scalar cols)
            {
                int c = e4 + lane;
                if (c < e) {
#pragma unroll
                    for (int r = 0; r < ROWS_PER_WARP; r++)
                        acc[r] += __ldcs(p + (size_t)r * SD + c);
                }
            }
        }
    } else {
        // remainder rows (B not multiple of 32): scalar per-row path
        for (int r = 0; r < nrows; r++) {
            const float* pr = p + (size_t)r * SD;
            float a = 0.f;
            for (int c = s + lane; c < e; c += 32) a += __ldcs(pr + c);
            acc[r] = a;
        }
    }

    // butterfly reduce all 8 accumulators
#pragma unroll
    for (int r = 0; r < ROWS_PER_WARP; r++) {
#pragma unroll
        for (int o = 16; o > 0; o >>= 1)
            acc[r] += __shfl_xor_sync(0xffffffffu, acc[r], o);
    }

    if (lane == 0) {
        const float inv_tau = 1.0f / 20.0f;
        size_t ob = (size_t)row0 * (size_t)K + g;
#pragma unroll
        for (int r = 0; r < ROWS_PER_WARP; r++)
            if (r < nrows) out[ob + (size_t)r * (size_t)K] = acc[r] * inv_tau;
    }
}

extern "C" void kernel_launch(void* const* d_in, const int* in_sizes, int n_in,
                              void* d_out, int out_size) {
    const float* x  = (const float*)d_in[0];
    const int*   gs = (const int*)d_in[1];

    int K = in_sizes[1];
    int B = out_size / K;
    int D = in_sizes[0] / B;

    float* out = (float*)d_out;

    pgs_scan_kernel<<<1, 1024>>>(gs, K);

    dim3 grid(K, (B + ROWS_PER_BLOCK - 1) / ROWS_PER_BLOCK);
    pgs_sum_kernel<<<grid, 128>>>(x, out, D, K, B);
}